// round 7
// baseline (speedup 1.0000x reference)
#include <cuda_runtime.h>
#include <cstdint>

// ---------------- problem constants ----------------
#define Hh  64
#define Ww  64
#define Cc  64
#define Uu  64
#define OHh 30
#define OWw 30
#define KDIM   1600           // 5*5*64
#define CW     16             // K-chunk width (floats)
#define NCHUNK 100            // KDIM / CW
#define LDSS   20             // smem row stride (pad 16->20): banks 20g+t all-distinct
#define NSTG   3              // pipeline stages

// Raw fp32 bits into the tf32 mma: HW reads the tf32 lanes of the register
// (truncation-to-tf32). Saves all cvt instructions in the mainloop.
__device__ __forceinline__ uint32_t tf32_bits(float v) { return __float_as_uint(v); }

__device__ __forceinline__ void mma_16n8k8(float c[4], const uint32_t a[4], const uint32_t b[2]) {
    asm volatile(
        "mma.sync.aligned.m16n8k8.row.col.f32.tf32.tf32.f32 "
        "{%0,%1,%2,%3}, {%4,%5,%6,%7}, {%8,%9}, {%0,%1,%2,%3};"
        : "+f"(c[0]), "+f"(c[1]), "+f"(c[2]), "+f"(c[3])
        : "r"(a[0]), "r"(a[1]), "r"(a[2]), "r"(a[3]), "r"(b[0]), "r"(b[1]));
}

__device__ __forceinline__ void cp16(uint32_t dst, const float* src) {
    asm volatile("cp.async.cg.shared.global [%0], [%1], 16;" :: "r"(dst), "l"(src));
}
// W is streaming / read-once: evict_first so it doesn't blow x out of L2.
__device__ __forceinline__ void cp16_ef(uint32_t dst, const float* src, uint64_t pol) {
    asm volatile("cp.async.cg.shared.global.L2::cache_hint [%0], [%1], 16, %2;"
                 :: "r"(dst), "l"(src), "l"(pol));
}
#define CP_COMMIT() asm volatile("cp.async.commit_group;" ::: "memory")

// ---------------- kernel ----------------
__global__ void __launch_bounds__(128, 6)
freeconv_mma_kernel(const float* __restrict__ x, const float* __restrict__ w,
                    const float* __restrict__ bias, float* __restrict__ out) {
    __shared__ float As[NSTG][64][LDSS];
    __shared__ float Bs[NSTG][64][LDSS];
    __shared__ float bsh[64];

    const int tid  = threadIdx.x;
    const int wid  = tid >> 5;
    const int lane = tid & 31;
    const int g    = lane >> 2;     // 0..7
    const int t    = lane & 3;      // 0..3
    const int tile = blockIdx.x;
    const int oh = tile / OWw, ow = tile % OWw;
    const int ih0 = oh * 2, iw0 = ow * 2;
    const int warpM = (wid >> 1) * 32;   // 0 or 32
    const int warpN = (wid & 1) * 32;    // 0 or 32

    uint64_t pol;
    asm("createpolicy.fractional.L2::evict_first.b64 %0, 1.0;" : "=l"(pol));

    if (tid < 64) bsh[tid] = bias[(size_t)tile * Uu + tid];

    const size_t wtile = (size_t)tile * Uu * KDIM;

    // Stage one K=16 chunk: A rows = 64 batches, B rows = 64 units, 64B/row.
    auto load_chunk = [&](int chunk, int s) {
        const int ij = chunk >> 2, q = chunk & 3;
        const int i = ij / 5, j = ij - i * 5;
        const float* xsrc = x + (((size_t)(ih0 + i) * Ww) + (iw0 + j)) * Cc + q * CW;
        const float* wsrc = w + wtile + (size_t)chunk * CW;
#pragma unroll
        for (int it = 0; it < 2; it++) {
            const int idx = tid + it * 128;      // 0..255
            const int row = idx >> 2, c16 = idx & 3;
            uint32_t ad = (uint32_t)__cvta_generic_to_shared(&As[s][row][0]) + c16 * 16;
            cp16(ad, xsrc + (size_t)row * (Hh * Ww * Cc) + c16 * 4);
            uint32_t bd = (uint32_t)__cvta_generic_to_shared(&Bs[s][row][0]) + c16 * 16;
            cp16_ef(bd, wsrc + (size_t)row * KDIM + c16 * 4, pol);
        }
    };

    float acc[2][4][4];
#pragma unroll
    for (int mt = 0; mt < 2; mt++)
#pragma unroll
        for (int nt = 0; nt < 4; nt++)
#pragma unroll
            for (int r = 0; r < 4; r++) acc[mt][nt][r] = 0.0f;

    // prologue: depth-2 prefetch
    load_chunk(0, 0); CP_COMMIT();
    load_chunk(1, 1); CP_COMMIT();

    int s = 0, s2 = 2;   // s = stage of chunk c; s2 = stage of chunk c+2
    for (int c = 0; c < NCHUNK; c++) {
        if (c + 1 < NCHUNK) {
            asm volatile("cp.async.wait_group 1;" ::: "memory");  // chunk c resident
        } else {
            asm volatile("cp.async.wait_group 0;" ::: "memory");
        }
        __syncthreads();   // chunk c visible to all; stage s2 fully consumed (c-1 done)

        if (c + 2 < NCHUNK) {
            load_chunk(c + 2, s2);
            CP_COMMIT();
        }

#pragma unroll
        for (int k8 = 0; k8 < 2; k8++) {
            const int kb = k8 * 8;
            uint32_t a[2][4], b[4][2];
#pragma unroll
            for (int mt = 0; mt < 2; mt++) {
                const int r0 = warpM + mt * 16 + g;
                a[mt][0] = tf32_bits(As[s][r0][kb + t]);
                a[mt][1] = tf32_bits(As[s][r0 + 8][kb + t]);
                a[mt][2] = tf32_bits(As[s][r0][kb + t + 4]);
                a[mt][3] = tf32_bits(As[s][r0 + 8][kb + t + 4]);
            }
#pragma unroll
            for (int nt = 0; nt < 4; nt++) {
                const int n0 = warpN + nt * 8 + g;
                b[nt][0] = tf32_bits(Bs[s][n0][kb + t]);
                b[nt][1] = tf32_bits(Bs[s][n0][kb + t + 4]);
            }
#pragma unroll
            for (int mt = 0; mt < 2; mt++)
#pragma unroll
                for (int nt = 0; nt < 4; nt++)
                    mma_16n8k8(acc[mt][nt], a[mt], b[nt]);
        }

        s  = (s  == NSTG - 1) ? 0 : s + 1;
        s2 = (s2 == NSTG - 1) ? 0 : s2 + 1;
    }

    // epilogue: D[row=m, col=u] += bias[u]; out[b][oh][ow][u]
#pragma unroll
    for (int mt = 0; mt < 2; mt++) {
        const int r0 = warpM + mt * 16 + g;
#pragma unroll
        for (int nt = 0; nt < 4; nt++) {
            const int col = warpN + nt * 8 + 2 * t;
            const float b0 = bsh[col], b1 = bsh[col + 1];
            float* op0 = out + (((size_t)r0 * OHh + oh) * OWw + ow) * Uu + col;
            float* op1 = out + (((size_t)(r0 + 8) * OHh + oh) * OWw + ow) * Uu + col;
            float2 v0 = make_float2(acc[mt][nt][0] + b0, acc[mt][nt][1] + b1);
            float2 v1 = make_float2(acc[mt][nt][2] + b0, acc[mt][nt][3] + b1);
            *reinterpret_cast<float2*>(op0) = v0;
            *reinterpret_cast<float2*>(op1) = v1;
        }
    }
}

// ---------------- launch ----------------
extern "C" void kernel_launch(void* const* d_in, const int* in_sizes, int n_in,
                              void* d_out, int out_size) {
    (void)in_sizes; (void)n_in; (void)out_size;
    const float* x = (const float*)d_in[0];
    const float* w = (const float*)d_in[1];
    const float* b = (const float*)d_in[2];
    freeconv_mma_kernel<<<OHh * OWw, 128>>>(x, w, b, (float*)d_out);
}

// round 8
// speedup vs baseline: 1.1128x; 1.1128x over previous
#include <cuda_runtime.h>
#include <cstdint>

// ---------------- problem constants ----------------
#define Hh  64
#define Ww  64
#define Cc  64
#define Uu  64
#define OHh 30
#define OWw 30
#define KDIM   1600           // 5*5*64
#define NCHUNK 50             // KDIM / 32
#define LDSS   36             // smem row stride in floats (bank=(4g+t)%32 -> conflict-free)

// Raw fp32 bits into the tf32 mma (truncation-to-tf32): no cvt in mainloop.
__device__ __forceinline__ uint32_t tf32_bits(float v) { return __float_as_uint(v); }

__device__ __forceinline__ void mma_16n8k8(float c[4], const uint32_t a[4], const uint32_t b[2]) {
    asm volatile(
        "mma.sync.aligned.m16n8k8.row.col.f32.tf32.tf32.f32 "
        "{%0,%1,%2,%3}, {%4,%5,%6,%7}, {%8,%9}, {%0,%1,%2,%3};"
        : "+f"(c[0]), "+f"(c[1]), "+f"(c[2]), "+f"(c[3])
        : "r"(a[0]), "r"(a[1]), "r"(a[2]), "r"(a[3]), "r"(b[0]), "r"(b[1]));
}

__device__ __forceinline__ void cp16(uint32_t dst, const float* src) {
    asm volatile("cp.async.cg.shared.global [%0], [%1], 16;" :: "r"(dst), "l"(src));
}
// W is streaming / read-once: evict_first so it doesn't blow x out of L2.
__device__ __forceinline__ void cp16_ef(uint32_t dst, const float* src, uint64_t pol) {
    asm volatile("cp.async.cg.shared.global.L2::cache_hint [%0], [%1], 16, %2;"
                 :: "r"(dst), "l"(src), "l"(pol));
}
#define CP_COMMIT()  asm volatile("cp.async.commit_group;" ::: "memory")
#define CP_WAIT0()   asm volatile("cp.async.wait_group 0;" ::: "memory")
#define CP_WAIT1()   asm volatile("cp.async.wait_group 1;" ::: "memory")

// ---------------- kernel ----------------
__global__ void __launch_bounds__(128, 6)
freeconv_mma_kernel(const float* __restrict__ x, const float* __restrict__ w,
                    const float* __restrict__ bias, float* __restrict__ out) {
    __shared__ float As[2][64][LDSS];
    __shared__ float Bs[2][64][LDSS];
    __shared__ float bsh[64];

    const int tid  = threadIdx.x;
    const int wid  = tid >> 5;
    const int lane = tid & 31;
    const int g    = lane >> 2;     // 0..7
    const int t    = lane & 3;      // 0..3
    const int tile = blockIdx.x;
    const int oh = tile / OWw, ow = tile % OWw;
    const int ih0 = oh * 2, iw0 = ow * 2;
    const int warpM = (wid >> 1) * 32;   // 0 or 32
    const int warpN = (wid & 1) * 32;    // 0 or 32

    uint64_t pol;
    asm("createpolicy.fractional.L2::evict_first.b64 %0, 1.0;" : "=l"(pol));

    if (tid < 64) bsh[tid] = bias[(size_t)tile * Uu + tid];

    const size_t wtile = (size_t)tile * Uu * KDIM;

    // Stage one K=32 chunk: A rows = 64 batches, B rows = 64 units, 128B/row.
    auto load_chunk = [&](int chunk, int s) {
        const int ij = chunk >> 1, ch = chunk & 1;
        const int i = ij / 5, j = ij - i * 5;
        const float* xsrc = x + (((size_t)(ih0 + i) * Ww) + (iw0 + j)) * Cc + ch * 32;
        const float* wsrc = w + wtile + (size_t)chunk * 32;
#pragma unroll
        for (int it = 0; it < 4; it++) {
            const int idx = tid + it * 128;      // 0..511
            const int row = idx >> 3, c16 = idx & 7;
            uint32_t ad = (uint32_t)__cvta_generic_to_shared(&As[s][row][0]) + c16 * 16;
            cp16(ad, xsrc + (size_t)row * (Hh * Ww * Cc) + c16 * 4);
            uint32_t bd = (uint32_t)__cvta_generic_to_shared(&Bs[s][row][0]) + c16 * 16;
            cp16_ef(bd, wsrc + (size_t)row * KDIM + c16 * 4, pol);
        }
    };

    float acc[2][4][4];
#pragma unroll
    for (int mt = 0; mt < 2; mt++)
#pragma unroll
        for (int nt = 0; nt < 4; nt++)
#pragma unroll
            for (int r = 0; r < 4; r++) acc[mt][nt][r] = 0.0f;

    // compute one resident chunk from stage s (compile-time)
    auto compute = [&](int s) {
#pragma unroll
        for (int k8 = 0; k8 < 4; k8++) {
            const int kb = k8 * 8;
            uint32_t a[2][4], b[4][2];
#pragma unroll
            for (int mt = 0; mt < 2; mt++) {
                const int r0 = warpM + mt * 16 + g;
                a[mt][0] = tf32_bits(As[s][r0][kb + t]);
                a[mt][1] = tf32_bits(As[s][r0 + 8][kb + t]);
                a[mt][2] = tf32_bits(As[s][r0][kb + t + 4]);
                a[mt][3] = tf32_bits(As[s][r0 + 8][kb + t + 4]);
            }
#pragma unroll
            for (int nt = 0; nt < 4; nt++) {
                const int n0 = warpN + nt * 8 + g;
                b[nt][0] = tf32_bits(Bs[s][n0][kb + t]);
                b[nt][1] = tf32_bits(Bs[s][n0][kb + t + 4]);
            }
#pragma unroll
            for (int mt = 0; mt < 2; mt++)
#pragma unroll
                for (int nt = 0; nt < 4; nt++)
                    mma_16n8k8(acc[mt][nt], a[mt], b[nt]);
        }
    };

    // prologue: chunks 0,1 committed; chunk 0 resident + visible
    load_chunk(0, 0); CP_COMMIT();
    load_chunk(1, 1); CP_COMMIT();
    CP_WAIT1();          // own part of chunk 0 done (chunk 1 still in flight)
    __syncthreads();     // chunk 0 visible to all

    // steady state: per chunk = 1 wait (post-compute) + 1 barrier
    for (int d = 0; d < NCHUNK / 2; d++) {
        const int c0 = 2 * d;

        compute(0);                       // chunk c0 (stage 0); c0+1 in flight
        CP_WAIT0();                       // own part of chunk c0+1 done
        __syncthreads();                  // c0+1 visible; everyone done reading stage 0
        if (c0 + 2 < NCHUNK) { load_chunk(c0 + 2, 0); CP_COMMIT(); }

        compute(1);                       // chunk c0+1 (stage 1); c0+2 in flight
        CP_WAIT0();                       // own part of chunk c0+2 done
        __syncthreads();                  // c0+2 visible; everyone done reading stage 1
        if (c0 + 3 < NCHUNK) { load_chunk(c0 + 3, 1); CP_COMMIT(); }
    }

    // epilogue: D[row=m, col=u] += bias[u]; out[b][oh][ow][u]
#pragma unroll
    for (int mt = 0; mt < 2; mt++) {
        const int r0 = warpM + mt * 16 + g;
#pragma unroll
        for (int nt = 0; nt < 4; nt++) {
            const int col = warpN + nt * 8 + 2 * t;
            const float b0 = bsh[col], b1 = bsh[col + 1];
            float* op0 = out + (((size_t)r0 * OHh + oh) * OWw + ow) * Uu + col;
            float* op1 = out + (((size_t)(r0 + 8) * OHh + oh) * OWw + ow) * Uu + col;
            float2 v0 = make_float2(acc[mt][nt][0] + b0, acc[mt][nt][1] + b1);
            float2 v1 = make_float2(acc[mt][nt][2] + b0, acc[mt][nt][3] + b1);
            *reinterpret_cast<float2*>(op0) = v0;
            *reinterpret_cast<float2*>(op1) = v1;
        }
    }
}

// ---------------- launch ----------------
extern "C" void kernel_launch(void* const* d_in, const int* in_sizes, int n_in,
                              void* d_out, int out_size) {
    (void)in_sizes; (void)n_in; (void)out_size;
    const float* x = (const float*)d_in[0];
    const float* w = (const float*)d_in[1];
    const float* b = (const float*)d_in[2];
    freeconv_mma_kernel<<<OHh * OWw, 128>>>(x, w, b, (float*)d_out);
}

// round 9
// speedup vs baseline: 1.1831x; 1.0632x over previous
#include <cuda_runtime.h>
#include <cstdint>

// ---------------- problem constants ----------------
#define Hh  64
#define Ww  64
#define Cc  64
#define Uu  64
#define OHh 30
#define OWw 30
#define KDIM   1600           // 5*5*64
#define NCHUNK 70             // union chunks: 5 i * 7 jj * 2 ch (two tiles per CTA)
#define LDSS   36             // smem row stride in floats (bank=(4g+t)%32 -> conflict-free)

// Raw fp32 bits into the tf32 mma (truncation-to-tf32): no cvt in mainloop.
__device__ __forceinline__ uint32_t tf32_bits(float v) { return __float_as_uint(v); }

__device__ __forceinline__ void mma_16n8k8(float c[4], const uint32_t a[4], const uint32_t b[2]) {
    asm volatile(
        "mma.sync.aligned.m16n8k8.row.col.f32.tf32.tf32.f32 "
        "{%0,%1,%2,%3}, {%4,%5,%6,%7}, {%8,%9}, {%0,%1,%2,%3};"
        : "+f"(c[0]), "+f"(c[1]), "+f"(c[2]), "+f"(c[3])
        : "r"(a[0]), "r"(a[1]), "r"(a[2]), "r"(a[3]), "r"(b[0]), "r"(b[1]));
}

__device__ __forceinline__ void cp16(uint32_t dst, const float* src) {
    asm volatile("cp.async.cg.shared.global [%0], [%1], 16;" :: "r"(dst), "l"(src));
}
// W is streaming / read-once: evict_first so it doesn't blow x out of L2.
__device__ __forceinline__ void cp16_ef(uint32_t dst, const float* src, uint64_t pol) {
    asm volatile("cp.async.cg.shared.global.L2::cache_hint [%0], [%1], 16, %2;"
                 :: "r"(dst), "l"(src), "l"(pol));
}
#define CP_COMMIT() asm volatile("cp.async.commit_group;" ::: "memory")

// ---------------- kernel ----------------
// One CTA computes TWO adjacent output columns (ow0, ow0+1): x patch columns
// overlap 3/5, so we iterate the union (7 jj columns); each position's warps
// are active for the 5 jj values inside its own window.
__global__ void __launch_bounds__(256, 3)
freeconv_mma_kernel(const float* __restrict__ x, const float* __restrict__ w,
                    const float* __restrict__ bias, float* __restrict__ out) {
    __shared__ float As[2][64][LDSS];        // x chunk (shared by both positions)
    __shared__ float Bs[2][2][64][LDSS];     // [stage][pos][u][k]
    __shared__ float bsh[128];               // bias for both positions

    const int tid  = threadIdx.x;
    const int wid  = tid >> 5;
    const int lane = tid & 31;
    const int g    = lane >> 2;     // 0..7
    const int t    = lane & 3;      // 0..3
    const int wg   = wid >> 2;      // position 0/1
    const int wl   = wid & 3;
    const int warpM = (wl >> 1) * 32;
    const int warpN = (wl & 1) * 32;

    const int oh  = blockIdx.x / (OWw / 2);
    const int pw  = blockIdx.x - oh * (OWw / 2);
    const int ow0 = pw * 2;
    const int ih0 = oh * 2, iw0 = ow0 * 2;
    const int tile0 = oh * OWw + ow0;

    uint64_t pol;
    asm("createpolicy.fractional.L2::evict_first.b64 %0, 1.0;" : "=l"(pol));

    if (tid < 128) bsh[tid] = bias[(size_t)tile0 * Uu + tid];

    const size_t wbase0 = (size_t)tile0 * Uu * KDIM;
    const size_t wbase1 = wbase0 + (size_t)Uu * KDIM;

    // Stage union chunk c = (i, jj, ch): A = x[:, ih0+i, iw0+jj, ch*32+0..31]
    auto load_chunk = [&](int c, int s) {
        const int i = c / 14, r = c - i * 14;
        const int jj = r >> 1, ch = r & 1;
        const float* xsrc = x + (((size_t)(ih0 + i) * Ww) + (iw0 + jj)) * Cc + ch * 32;
#pragma unroll
        for (int it = 0; it < 2; it++) {
            const int idx = tid + it * 256;      // 0..511
            const int row = idx >> 3, c16 = idx & 7;
            uint32_t ad = (uint32_t)__cvta_generic_to_shared(&As[s][row][0]) + c16 * 16;
            cp16(ad, xsrc + (size_t)row * (Hh * Ww * Cc) + c16 * 4);
        }
        if (jj <= 4) {                 // position 0 weights: local j = jj
            const int k0 = (i * 5 + jj) * 2 + ch;
            const float* wsrc = w + wbase0 + (size_t)k0 * 32;
#pragma unroll
            for (int it = 0; it < 2; it++) {
                const int idx = tid + it * 256;
                const int row = idx >> 3, c16 = idx & 7;
                uint32_t bd = (uint32_t)__cvta_generic_to_shared(&Bs[s][0][row][0]) + c16 * 16;
                cp16_ef(bd, wsrc + (size_t)row * KDIM + c16 * 4, pol);
            }
        }
        if (jj >= 2) {                 // position 1 weights: local j = jj-2
            const int k1 = (i * 5 + (jj - 2)) * 2 + ch;
            const float* wsrc = w + wbase1 + (size_t)k1 * 32;
#pragma unroll
            for (int it = 0; it < 2; it++) {
                const int idx = tid + it * 256;
                const int row = idx >> 3, c16 = idx & 7;
                uint32_t bd = (uint32_t)__cvta_generic_to_shared(&Bs[s][1][row][0]) + c16 * 16;
                cp16_ef(bd, wsrc + (size_t)row * KDIM + c16 * 4, pol);
            }
        }
    };

    float acc[2][4][4];
#pragma unroll
    for (int mt = 0; mt < 2; mt++)
#pragma unroll
        for (int nt = 0; nt < 4; nt++)
#pragma unroll
            for (int r = 0; r < 4; r++) acc[mt][nt][r] = 0.0f;

    load_chunk(0, 0);
    CP_COMMIT();

    for (int c = 0; c < NCHUNK; c++) {
        const int s = c & 1;
        if (c + 1 < NCHUNK) {
            load_chunk(c + 1, s ^ 1);
            CP_COMMIT();
            asm volatile("cp.async.wait_group 1;" ::: "memory");
        } else {
            asm volatile("cp.async.wait_group 0;" ::: "memory");
        }
        __syncthreads();

        // this position active for this union column?
        const int jj = (c - (c / 14) * 14) >> 1;
        const bool active = wg ? (jj >= 2) : (jj <= 4);
        if (active) {
#pragma unroll
            for (int k8 = 0; k8 < 4; k8++) {
                const int kb = k8 * 8;
                uint32_t a[2][4], b[4][2];
#pragma unroll
                for (int mt = 0; mt < 2; mt++) {
                    const int r0 = warpM + mt * 16 + g;
                    a[mt][0] = tf32_bits(As[s][r0][kb + t]);
                    a[mt][1] = tf32_bits(As[s][r0 + 8][kb + t]);
                    a[mt][2] = tf32_bits(As[s][r0][kb + t + 4]);
                    a[mt][3] = tf32_bits(As[s][r0 + 8][kb + t + 4]);
                }
#pragma unroll
                for (int nt = 0; nt < 4; nt++) {
                    const int n0 = warpN + nt * 8 + g;
                    b[nt][0] = tf32_bits(Bs[s][wg][n0][kb + t]);
                    b[nt][1] = tf32_bits(Bs[s][wg][n0][kb + t + 4]);
                }
#pragma unroll
                for (int mt = 0; mt < 2; mt++)
#pragma unroll
                    for (int nt = 0; nt < 4; nt++)
                        mma_16n8k8(acc[mt][nt], a[mt], b[nt]);
            }
        }
        __syncthreads();
    }

    // epilogue: warp-group wg writes tile (oh, ow0+wg)
    const int owp = ow0 + wg;
#pragma unroll
    for (int mt = 0; mt < 2; mt++) {
        const int r0 = warpM + mt * 16 + g;
#pragma unroll
        for (int nt = 0; nt < 4; nt++) {
            const int col = warpN + nt * 8 + 2 * t;
            const float b0 = bsh[wg * 64 + col], b1 = bsh[wg * 64 + col + 1];
            float* op0 = out + (((size_t)r0 * OHh + oh) * OWw + owp) * Uu + col;
            float* op1 = out + (((size_t)(r0 + 8) * OHh + oh) * OWw + owp) * Uu + col;
            float2 v0 = make_float2(acc[mt][nt][0] + b0, acc[mt][nt][1] + b1);
            float2 v1 = make_float2(acc[mt][nt][2] + b0, acc[mt][nt][3] + b1);
            *reinterpret_cast<float2*>(op0) = v0;
            *reinterpret_cast<float2*>(op1) = v1;
        }
    }
}

// ---------------- launch ----------------
extern "C" void kernel_launch(void* const* d_in, const int* in_sizes, int n_in,
                              void* d_out, int out_size) {
    (void)in_sizes; (void)n_in; (void)out_size;
    const float* x = (const float*)d_in[0];
    const float* w = (const float*)d_in[1];
    const float* b = (const float*)d_in[2];
    freeconv_mma_kernel<<<OHh * (OWw / 2), 256>>>(x, w, b, (float*)d_out);
}